// round 12
// baseline (speedup 1.0000x reference)
#include <cuda_runtime.h>
#include <cstdint>
#include <cstddef>

// ============================================================================
// RhythmMemoryUpdater — GB300 sm_103a (base sm_103 target: mma.sync tf32 path)
//   L = 1  =>  out = node_memories; out[node_ids] = LN( x @ W'^T + lin_b )
//   x = [messages | node_memories[node_ids]] (K=256)
//   W'[d,c] = lin_w[d,c] * conv_w[c, period/2]
//
// R12: single persistent kernel does GEMM **and** the masked copy.
//   16 warps: K split across warp pairs. Per iteration:
//     - all warps: MMA (tf32, W' in regs, x via 2-stage cp.async pipeline)
//     - kh1 warps: publish K-high partials, then COPY a slice of the
//       non-updated rows (overlaps kh0's epilogue; uses idle DRAM)
//     - kh0 warps: combine + bias + LayerNorm + coalesced scatter
// ============================================================================

#define NDIM 128
#define KDIM 256
#define TILE_M 64
#define NTHREADS 512
#define NCTAS 148
#define NSLOTS 4                 // node-id ring depth
#define SX_STRIDE 260            // floats per staged x row (1040B)
#define SD_STRIDE 132            // floats per D row (conflict-free)

__device__ uint8_t g_mask[1 << 20];

// ---------------- helpers ----------------
__device__ __forceinline__ uint32_t smem_u32(const void* p) {
    uint32_t a;
    asm("{ .reg .u64 t; cvta.to.shared.u64 t, %1; cvt.u32.u64 %0, t; }" : "=r"(a) : "l"(p));
    return a;
}
__device__ __forceinline__ uint32_t f2tf32(float f) {
    uint32_t o;
    asm("cvt.rna.tf32.f32 %0, %1;" : "=r"(o) : "f"(f));
    return o;
}
__device__ __forceinline__ void mma_tf32(float c[4], uint32_t a0, uint32_t a1,
                                         uint32_t a2, uint32_t a3,
                                         uint32_t b0, uint32_t b1) {
    asm volatile(
        "mma.sync.aligned.m16n8k8.row.col.f32.tf32.tf32.f32 "
        "{%0,%1,%2,%3}, {%4,%5,%6,%7}, {%8,%9}, {%0,%1,%2,%3};"
        : "+f"(c[0]), "+f"(c[1]), "+f"(c[2]), "+f"(c[3])
        : "r"(a0), "r"(a1), "r"(a2), "r"(a3), "r"(b0), "r"(b1));
}
__device__ __forceinline__ void cp_async16(uint32_t dst, const void* src) {
    asm volatile("cp.async.cg.shared.global [%0], [%1], 16;" :: "r"(dst), "l"(src));
}
#define CP_COMMIT() asm volatile("cp.async.commit_group;" ::: "memory")
#define CP_WAIT1()  asm volatile("cp.async.wait_group 1;" ::: "memory")

// named barrier among the 256 kh0 threads (tid 0..255)
#define KH0_BAR() asm volatile("bar.sync 1, 256;" ::: "memory")

// ============================================================================
// mask kernels
// ============================================================================
__global__ void __launch_bounds__(256) k_clear(int nbytes16) {
    uint4 z = make_uint4(0, 0, 0, 0);
    uint4* m = (uint4*)g_mask;
    for (int i = blockIdx.x * 256 + threadIdx.x; i < nbytes16; i += gridDim.x * 256)
        m[i] = z;
}
__global__ void __launch_bounds__(256) k_mark(const int* __restrict__ ids, int n) {
    int i = blockIdx.x * 256 + threadIdx.x;
    if (i < n) g_mask[ids[i]] = 1;
}

// ============================================================================
// fused persistent GEMM + LayerNorm + scatter + masked copy
// ============================================================================
__global__ void __launch_bounds__(NTHREADS, 1) rhythm_gemm(
    const int*   __restrict__ node_ids,
    const float* __restrict__ messages,
    const float* __restrict__ node_mem,
    const float* __restrict__ conv_w,
    const float* __restrict__ lin_w,
    const float* __restrict__ lin_b,
    const float* __restrict__ ln_g,
    const float* __restrict__ ln_bt,
    float*       __restrict__ out,
    int ntiles, int period, int pad, int nf4)
{
    // ---- dynamic smem carve ----
    extern __shared__ float dyn[];
    float*  sX     = dyn;                                       // 2*64*260 f
    float4* s_comb = (float4*)(dyn + 2 * TILE_M * SX_STRIDE);   // 2048 f4
    float*  sD     = dyn + 2 * TILE_M * SX_STRIDE + 8192;       // 64*132 f
    int*    s_node = (int*)(sD + TILE_M * SD_STRIDE);           // 4*64
    float*  s_gam  = (float*)(s_node + NSLOTS * TILE_M);        // 128
    float*  s_bet  = s_gam + NDIM;                              // 128

    const int tid  = threadIdx.x;
    const int lane = tid & 31;
    const int wid  = tid >> 5;        // 0..15
    const int kh   = wid >> 3;        // K-half
    const int dblk = wid & 7;         // d block

    // ---- static per-warp W' fragments (A operand of C^T = W' * x^T) ----
    const int d1 = dblk * 16 + (lane >> 2);
    const int d2 = d1 + 8;
    const int kbase = lane & 3;

    uint32_t areg[16][4];
#pragma unroll
    for (int kt = 0; kt < 16; kt++) {
        int k1 = kh * 128 + kt * 8 + kbase, k2 = k1 + 4;
        float w1 = __ldg(conv_w + k1 * period + pad);
        float w2 = __ldg(conv_w + k2 * period + pad);
        areg[kt][0] = f2tf32(__ldg(lin_w + d1 * KDIM + k1) * w1);
        areg[kt][1] = f2tf32(__ldg(lin_w + d2 * KDIM + k1) * w1);
        areg[kt][2] = f2tf32(__ldg(lin_w + d1 * KDIM + k2) * w2);
        areg[kt][3] = f2tf32(__ldg(lin_w + d2 * KDIM + k2) * w2);
    }
    const float bia1 = __ldg(lin_b + d1), bia2 = __ldg(lin_b + d2);
    if (tid < NDIM) {
        s_gam[tid] = ln_g[tid];
        s_bet[tid] = ln_bt[tid];
    }

    // ---- per-CTA copy assignment ----
    const int per_cta = (nf4 + NCTAS - 1) / NCTAS;
    const long long cbase = (long long)blockIdx.x * per_cta;
    const long long cend0 = cbase + per_cta;
    const long long cend  = cend0 < (long long)nf4 ? cend0 : (long long)nf4;
    const int nt_cta = (ntiles - (int)blockIdx.x + NCTAS - 1) / NCTAS;  // tiles this CTA runs
    int slice = nt_cta > 0 ? (per_cta + nt_cta - 1) / nt_cta : 0;
    slice = ((slice + 255) / 256) * 256;     // keep 256-thread alignment
    const float4* src4 = (const float4*)node_mem;
    float4*       dst4 = (float4*)out;

    // ---- cp.async stage: 64 rows x 256 floats ----
    auto stage_tile = [&](int tile, int it_idx) {
        if (tile >= ntiles) return;
        const int dslot = it_idx & 1;
        const int nslot = it_idx & (NSLOTS - 1);
        float* dstS = sX + (size_t)dslot * TILE_M * SX_STRIDE;
#pragma unroll
        for (int i = 0; i < 8; i++) {
            int idx = i * NTHREADS + tid;     // 4096 chunks of 16B
            int row = idx >> 6, c = idx & 63;
            long long gr = (long long)tile * TILE_M + row;
            const float4* src;
            if (c < 32) {
                src = (const float4*)messages + gr * 32 + c;
            } else {
                int nd = __ldg(node_ids + gr);
                if (c == 32) s_node[nslot * TILE_M + row] = nd;
                src = (const float4*)node_mem + (long long)nd * 32 + (c - 32);
            }
            cp_async16(smem_u32(dstS + row * SX_STRIDE + c * 4), src);
        }
    };

    // ---- prologue ----
    stage_tile(blockIdx.x, 0);
    CP_COMMIT();
    stage_tile(blockIdx.x + gridDim.x, 1);
    CP_COMMIT();

    for (int it = 0;; it++) {
        int tile = blockIdx.x + it * gridDim.x;
        if (tile >= ntiles) break;
        const int dslot = it & 1;
        const int nslot = it & (NSLOTS - 1);

        CP_WAIT1();
        __syncthreads();          // staged slot + s_node (+ s_gam first iter)
                                  // also: prev iter's sD/s_comb fully consumed

        // ======== MMA: per warp 16 d x 64 batch, K-half ========
        const float* xb = sX + (size_t)dslot * TILE_M * SX_STRIDE
                        + (lane >> 2) * SX_STRIDE + kh * 128 + kbase;
        float cacc[8][4];
#pragma unroll
        for (int nt = 0; nt < 8; nt++)
#pragma unroll
            for (int j = 0; j < 4; j++) cacc[nt][j] = 0.f;

#pragma unroll
        for (int kt = 0; kt < 16; kt++) {
            uint32_t b[16];
#pragma unroll
            for (int nt = 0; nt < 8; nt++) {
                const float* xp = xb + nt * 8 * SX_STRIDE + kt * 8;
                b[2 * nt]     = f2tf32(xp[0]);
                b[2 * nt + 1] = f2tf32(xp[4]);
            }
#pragma unroll
            for (int nt = 0; nt < 8; nt++)
                mma_tf32(cacc[nt], areg[kt][0], areg[kt][1],
                         areg[kt][2], areg[kt][3], b[2 * nt], b[2 * nt + 1]);
        }

        // ---- K-high warps publish partials ----
        if (kh == 1) {
#pragma unroll
            for (int nt = 0; nt < 8; nt++)
                s_comb[(dblk * 8 + nt) * 32 + lane] =
                    make_float4(cacc[nt][0], cacc[nt][1], cacc[nt][2], cacc[nt][3]);
        }
        __syncthreads();          // sX slot free + s_comb visible

        // ---- prefetch tile it+2 into the freed data slot (cheap issue) ----
        stage_tile(tile + 2 * gridDim.x, it + 2);
        CP_COMMIT();

        if (kh == 1) {
            // ============ kh1: masked copy slice (overlaps kh0 epilogue) ===
            long long start = cbase + (long long)it * slice;
            long long stop  = start + slice;
            if (stop > cend) stop = cend;
#pragma unroll 4
            for (long long i = start + (tid - 256); i < stop; i += 256) {
                int row = (int)(i >> 5);
                if (g_mask[row] == 0) dst4[i] = src4[i];
            }
        } else {
            // ============ kh0: combine + bias -> sD =======================
#pragma unroll
            for (int nt = 0; nt < 8; nt++) {
                float4 p = s_comb[(dblk * 8 + nt) * 32 + lane];
                int brA = nt * 8 + (lane & 3) * 2;
                sD[brA * SD_STRIDE + d1]       = cacc[nt][0] + p.x + bia1;
                sD[(brA + 1) * SD_STRIDE + d1] = cacc[nt][1] + p.y + bia1;
                sD[brA * SD_STRIDE + d2]       = cacc[nt][2] + p.z + bia2;
                sD[(brA + 1) * SD_STRIDE + d2] = cacc[nt][3] + p.w + bia2;
            }
            KH0_BAR();            // sD complete (kh0-only barrier)

            // ============ kh0: LayerNorm + coalesced scatter (2 passes) ====
#pragma unroll
            for (int p = 0; p < 2; p++) {
                const int r  = p * 32 + (tid >> 3);   // row 0..63
                const int cc = tid & 7;               // f4-chunks cc,cc+8,cc+16,cc+24
                float4 v[4];
                float vsum = 0.f, vsq = 0.f;
#pragma unroll
                for (int j = 0; j < 4; j++) {
                    v[j] = *(const float4*)&sD[r * SD_STRIDE + (cc + 8 * j) * 4];
                    vsum += v[j].x + v[j].y + v[j].z + v[j].w;
                    vsq  += v[j].x * v[j].x + v[j].y * v[j].y
                          + v[j].z * v[j].z + v[j].w * v[j].w;
                }
                vsum += __shfl_xor_sync(0xffffffffu, vsum, 1);
                vsq  += __shfl_xor_sync(0xffffffffu, vsq, 1);
                vsum += __shfl_xor_sync(0xffffffffu, vsum, 2);
                vsq  += __shfl_xor_sync(0xffffffffu, vsq, 2);
                vsum += __shfl_xor_sync(0xffffffffu, vsum, 4);
                vsq  += __shfl_xor_sync(0xffffffffu, vsq, 4);
                float mean = vsum * (1.0f / 128.0f);
                float var  = vsq * (1.0f / 128.0f) - mean * mean;
                float rstd = rsqrtf(var + 1e-5f);

                long long nd = s_node[nslot * TILE_M + r];
                float* orow = out + nd * NDIM;
#pragma unroll
                for (int j = 0; j < 4; j++) {
                    int cb = (cc + 8 * j) * 4;
                    const float4 g  = *(const float4*)&s_gam[cb];
                    const float4 bt = *(const float4*)&s_bet[cb];
                    float4 o;
                    o.x = (v[j].x - mean) * rstd * g.x + bt.x;
                    o.y = (v[j].y - mean) * rstd * g.y + bt.y;
                    o.z = (v[j].z - mean) * rstd * g.z + bt.z;
                    o.w = (v[j].w - mean) * rstd * g.w + bt.w;
                    *(float4*)&orow[cb] = o;
                }
            }
        }
        // loop-top __syncthreads rejoins kh0/kh1 and protects sD/s_comb/sX
    }
}

// ============================================================================
// launch
// ============================================================================
extern "C" void kernel_launch(void* const* d_in, const int* in_sizes, int n_in,
                              void* d_out, int out_size) {
    const int*   node_ids = (const int*)  d_in[0];
    const float* messages = (const float*)d_in[1];
    const float* node_mem = (const float*)d_in[2];
    const float* conv_w   = (const float*)d_in[3];
    const float* lin_w    = (const float*)d_in[4];
    const float* lin_b    = (const float*)d_in[5];
    const float* ln_g     = (const float*)d_in[6];
    const float* ln_bt    = (const float*)d_in[7];
    float* out = (float*)d_out;

    int Btot    = in_sizes[1] / NDIM;            // 262144
    int ntiles  = Btot / TILE_M;                 // 4096
    int period  = in_sizes[3] / KDIM;            // 7
    int pad     = period / 2;                    // 3 (L == 1 path)
    int nf4     = out_size / 4;                  // 32M float4

    // mask of rows updated by the scatter
    k_clear<<<64, 256>>>((1 << 20) / 16);
    k_mark<<<(Btot + 255) / 256, 256>>>(node_ids, Btot);

    // fused persistent GEMM + LN + scatter + masked copy
    const int dyn_smem = (2 * TILE_M * SX_STRIDE + 8192 + TILE_M * SD_STRIDE) * 4
                       + NSLOTS * TILE_M * 4 + 2 * NDIM * 4;   // ~202 KB
    static int configured = -1;
    if (configured != dyn_smem) {
        cudaFuncSetAttribute(rhythm_gemm, cudaFuncAttributeMaxDynamicSharedMemorySize,
                             dyn_smem);
        configured = dyn_smem;
    }
    rhythm_gemm<<<NCTAS, NTHREADS, dyn_smem>>>(node_ids, messages, node_mem, conv_w,
                                               lin_w, lin_b, ln_g, ln_bt, out,
                                               ntiles, period, pad, nf4);
}

// round 14
// speedup vs baseline: 1.9286x; 1.9286x over previous
#include <cuda_runtime.h>
#include <cstdint>
#include <cstddef>

// ============================================================================
// RhythmMemoryUpdater — GB300 sm_103a (base sm_103 target: mma.sync tf32 path)
//   L = 1  =>  out = node_memories; out[node_ids] = LN( x @ W'^T + lin_b )
//   x = [messages | node_memories[node_ids]] (K=256)
//   W'[d,c] = lin_w[d,c] * conv_w[c, period/2]
//
// k_clear/k_mark: byte mask of updated node rows
// k_copy_masked:  high-occupancy copy of non-updated rows (separate kernel)
// rhythm_gemm:    persistent 148-CTA, 512-thread GEMM. 16 warps, K split
//                 across warp pairs. kh1 warps are staging/convert
//                 specialists (cp.async + tf32 pair-permute) overlapped with
//                 kh0's epilogue. MMA inner loop: conflict-free LDS.64+HMMA.
//                 R14 fix: kh1 named barrier after wait_group before convert
//                 (cp.async completion is only visible to the issuing thread;
//                 the convert pass reads other threads' staged bytes).
// ============================================================================

#define NDIM 128
#define KDIM 256
#define TILE_M 64
#define NTHREADS 512
#define NCTAS 148
#define NSLOTS 4                 // node-id ring depth
#define SX_STRIDE 264            // u32 per staged row: conflict-free LDS.64
#define SD_STRIDE 132            // floats per D row (conflict-free)

__device__ uint8_t g_mask[1 << 20];

// ---------------- helpers ----------------
__device__ __forceinline__ uint32_t smem_u32(const void* p) {
    uint32_t a;
    asm("{ .reg .u64 t; cvta.to.shared.u64 t, %1; cvt.u32.u64 %0, t; }" : "=r"(a) : "l"(p));
    return a;
}
__device__ __forceinline__ uint32_t f2tf32(float f) {
    uint32_t o;
    asm("cvt.rna.tf32.f32 %0, %1;" : "=r"(o) : "f"(f));
    return o;
}
__device__ __forceinline__ void mma_tf32(float c[4], uint32_t a0, uint32_t a1,
                                         uint32_t a2, uint32_t a3,
                                         uint32_t b0, uint32_t b1) {
    asm volatile(
        "mma.sync.aligned.m16n8k8.row.col.f32.tf32.tf32.f32 "
        "{%0,%1,%2,%3}, {%4,%5,%6,%7}, {%8,%9}, {%0,%1,%2,%3};"
        : "+f"(c[0]), "+f"(c[1]), "+f"(c[2]), "+f"(c[3])
        : "r"(a0), "r"(a1), "r"(a2), "r"(a3), "r"(b0), "r"(b1));
}
__device__ __forceinline__ void cp_async16(uint32_t dst, const void* src) {
    asm volatile("cp.async.cg.shared.global [%0], [%1], 16;" :: "r"(dst), "l"(src));
}
#define CP_COMMIT() asm volatile("cp.async.commit_group;" ::: "memory")
#define CP_WAIT1()  asm volatile("cp.async.wait_group 1;" ::: "memory")

// named barrier among the 256 kh0 threads (tid 0..255)
#define KH0_BAR() asm volatile("bar.sync 1, 256;" ::: "memory")
// named barrier among the 256 kh1 threads (tid 256..511)
#define KH1_BAR() asm volatile("bar.sync 2, 256;" ::: "memory")

// ============================================================================
// mask + copy kernels
// ============================================================================
__global__ void __launch_bounds__(256) k_clear(int nbytes16) {
    uint4 z = make_uint4(0, 0, 0, 0);
    uint4* m = (uint4*)g_mask;
    for (int i = blockIdx.x * 256 + threadIdx.x; i < nbytes16; i += gridDim.x * 256)
        m[i] = z;
}
__global__ void __launch_bounds__(256) k_mark(const int* __restrict__ ids, int n) {
    int i = blockIdx.x * 256 + threadIdx.x;
    if (i < n) g_mask[ids[i]] = 1;
}
__global__ void __launch_bounds__(256) k_copy_masked(const float4* __restrict__ src,
                                                     float4* __restrict__ dst,
                                                     int nf4) {
    int stride = gridDim.x * 256;
    for (int i = blockIdx.x * 256 + threadIdx.x; i < nf4; i += stride) {
        int row = i >> 5;
        if (g_mask[row] == 0) dst[i] = src[i];
    }
}

// ============================================================================
// persistent GEMM + LayerNorm + scatter
// ============================================================================
__global__ void __launch_bounds__(NTHREADS, 1) rhythm_gemm(
    const int*   __restrict__ node_ids,
    const float* __restrict__ messages,
    const float* __restrict__ node_mem,
    const float* __restrict__ conv_w,
    const float* __restrict__ lin_w,
    const float* __restrict__ lin_b,
    const float* __restrict__ ln_g,
    const float* __restrict__ ln_bt,
    float*       __restrict__ out,
    int ntiles, int period, int pad)
{
    // ---- dynamic smem carve ----
    extern __shared__ uint32_t dyn[];
    uint32_t* sX     = dyn;                                     // 2*64*264 u32
    float4*   s_comb = (float4*)(dyn + 2 * TILE_M * SX_STRIDE); // 2048 f4
    float*    sD     = (float*)(s_comb + 2048);                 // 64*132 f
    int*      s_node = (int*)(sD + TILE_M * SD_STRIDE);         // 4*64
    float*    s_gam  = (float*)(s_node + NSLOTS * TILE_M);      // 128
    float*    s_bet  = s_gam + NDIM;                            // 128

    const int tid  = threadIdx.x;
    const int lane = tid & 31;
    const int wid  = tid >> 5;        // 0..15
    const int kh   = wid >> 3;        // K-half
    const int dblk = wid & 7;         // d block

    // ---- static per-warp W' fragments (A operand of C^T = W' * x^T) ----
    const int d1 = dblk * 16 + (lane >> 2);
    const int d2 = d1 + 8;
    const int kbase = lane & 3;

    uint32_t areg[16][4];
#pragma unroll
    for (int kt = 0; kt < 16; kt++) {
        int k1 = kh * 128 + kt * 8 + kbase, k2 = k1 + 4;
        float w1 = __ldg(conv_w + k1 * period + pad);
        float w2 = __ldg(conv_w + k2 * period + pad);
        areg[kt][0] = f2tf32(__ldg(lin_w + d1 * KDIM + k1) * w1);
        areg[kt][1] = f2tf32(__ldg(lin_w + d2 * KDIM + k1) * w1);
        areg[kt][2] = f2tf32(__ldg(lin_w + d1 * KDIM + k2) * w2);
        areg[kt][3] = f2tf32(__ldg(lin_w + d2 * KDIM + k2) * w2);
    }
    const float bia1 = __ldg(lin_b + d1), bia2 = __ldg(lin_b + d2);
    if (tid < NDIM) {
        s_gam[tid] = ln_g[tid];
        s_bet[tid] = ln_bt[tid];
    }

    // ---- kh1-only: cp.async stage of raw x (64 rows x 64 f4 chunks) ----
    auto stage_tile = [&](int tile, int it_idx) {
        if (tile >= ntiles) return;
        const int dslot = it_idx & 1;
        const int nslot = it_idx & (NSLOTS - 1);
        uint32_t* dstS = sX + (size_t)dslot * TILE_M * SX_STRIDE;
        const int t = tid - 256;          // 0..255
#pragma unroll
        for (int i = 0; i < 16; i++) {
            int idx = i * 256 + t;        // 4096 chunks of 16B
            int row = idx >> 6, c = idx & 63;
            long long gr = (long long)tile * TILE_M + row;
            const float4* src;
            if (c < 32) {
                src = (const float4*)messages + gr * 32 + c;
            } else {
                int nd = __ldg(node_ids + gr);
                if (c == 32) s_node[nslot * TILE_M + row] = nd;
                src = (const float4*)node_mem + (long long)nd * 32 + (c - 32);
            }
            cp_async16(smem_u32(dstS + row * SX_STRIDE + c * 4), src);
        }
    };

    // ---- kh1-only: convert+permute a staged slot to paired tf32 ----
    //      group = 8 floats (k..k+7) -> u32[2j]=tf32(k+j), u32[2j+1]=tf32(k+j+4)
    auto convert_slot = [&](int it_idx) {
        uint32_t* slotS = sX + (size_t)(it_idx & 1) * TILE_M * SX_STRIDE;
        const int t = tid - 256;          // 0..255
#pragma unroll
        for (int i = 0; i < 8; i++) {
            int g = i * 256 + t;          // 2048 groups
            int row = g >> 5, kg = g & 31;
            uint32_t* p = slotS + row * SX_STRIDE + kg * 8;
            float4 f0 = *(float4*)p;
            float4 f1 = *(float4*)(p + 4);
            uint4 u0 = make_uint4(f2tf32(f0.x), f2tf32(f1.x),
                                  f2tf32(f0.y), f2tf32(f1.y));
            uint4 u1 = make_uint4(f2tf32(f0.z), f2tf32(f1.z),
                                  f2tf32(f0.w), f2tf32(f1.w));
            *(uint4*)p = u0;
            *(uint4*)(p + 4) = u1;
        }
    };

    // ---- prologue: kh1 stages tiles 0,1 and converts tile 0 ----
    if (kh == 1) {
        stage_tile(blockIdx.x, 0);
        CP_COMMIT();
        stage_tile(blockIdx.x + gridDim.x, 1);
        CP_COMMIT();
        CP_WAIT1();                       // this thread's tile-0 chunks landed
        KH1_BAR();                        // ALL kh1 threads' chunks visible
        if (blockIdx.x < ntiles) convert_slot(0);
    }

    for (int it = 0;; it++) {
        int tile = blockIdx.x + it * gridDim.x;
        if (tile >= ntiles) break;
        const int dslot = it & 1;
        const int nslot = it & (NSLOTS - 1);

        __syncthreads();          // converted slot + s_node visible
                                  // prev iter's sD/s_comb fully consumed

        // ======== MMA: per warp 16 d x 64 batch, K-half ========
        // b pair (k, k+4) for batch-col bn = (lane>>2)+nt*8 is ONE u64
        const uint32_t* xb = sX + (size_t)dslot * TILE_M * SX_STRIDE
                           + (lane >> 2) * SX_STRIDE + kh * 128 + kbase * 2;
        float cacc[8][4];
#pragma unroll
        for (int nt = 0; nt < 8; nt++)
#pragma unroll
            for (int j = 0; j < 4; j++) cacc[nt][j] = 0.f;

#pragma unroll
        for (int kt = 0; kt < 16; kt++) {
            uint2 bp[8];
#pragma unroll
            for (int nt = 0; nt < 8; nt++)
                bp[nt] = *(const uint2*)(xb + nt * 8 * SX_STRIDE + kt * 8);
#pragma unroll
            for (int nt = 0; nt < 8; nt++)
                mma_tf32(cacc[nt], areg[kt][0], areg[kt][1],
                         areg[kt][2], areg[kt][3], bp[nt].x, bp[nt].y);
        }

        // ---- K-high warps publish partials ----
        if (kh == 1) {
#pragma unroll
            for (int nt = 0; nt < 8; nt++)
                s_comb[(dblk * 8 + nt) * 32 + lane] =
                    make_float4(cacc[nt][0], cacc[nt][1], cacc[nt][2], cacc[nt][3]);
        }
        __syncthreads();          // sX slot free + s_comb visible

        if (kh == 1) {
            // ===== kh1: stage tile it+2, wait for it+1, convert it+1 =====
            stage_tile(tile + 2 * gridDim.x, it + 2);
            CP_COMMIT();
            CP_WAIT1();           // this thread's tile-(it+1) chunks landed
            KH1_BAR();            // ALL kh1 threads' chunks visible
            if (tile + gridDim.x < ntiles) convert_slot(it + 1);
        } else {
            // ============ kh0: combine + bias -> sD =======================
#pragma unroll
            for (int nt = 0; nt < 8; nt++) {
                float4 p = s_comb[(dblk * 8 + nt) * 32 + lane];
                int brA = nt * 8 + (lane & 3) * 2;
                sD[brA * SD_STRIDE + d1]       = cacc[nt][0] + p.x + bia1;
                sD[(brA + 1) * SD_STRIDE + d1] = cacc[nt][1] + p.y + bia1;
                sD[brA * SD_STRIDE + d2]       = cacc[nt][2] + p.z + bia2;
                sD[(brA + 1) * SD_STRIDE + d2] = cacc[nt][3] + p.w + bia2;
            }
            KH0_BAR();            // sD complete (kh0-only barrier)

            // ============ kh0: LayerNorm + coalesced scatter (2 passes) ====
#pragma unroll
            for (int p = 0; p < 2; p++) {
                const int r  = p * 32 + (tid >> 3);   // row 0..63
                const int cc = tid & 7;               // f4-chunks cc,cc+8,cc+16,cc+24
                float4 v[4];
                float vsum = 0.f, vsq = 0.f;
#pragma unroll
                for (int j = 0; j < 4; j++) {
                    v[j] = *(const float4*)&sD[r * SD_STRIDE + (cc + 8 * j) * 4];
                    vsum += v[j].x + v[j].y + v[j].z + v[j].w;
                    vsq  += v[j].x * v[j].x + v[j].y * v[j].y
                          + v[j].z * v[j].z + v[j].w * v[j].w;
                }
                vsum += __shfl_xor_sync(0xffffffffu, vsum, 1);
                vsq  += __shfl_xor_sync(0xffffffffu, vsq, 1);
                vsum += __shfl_xor_sync(0xffffffffu, vsum, 2);
                vsq  += __shfl_xor_sync(0xffffffffu, vsq, 2);
                vsum += __shfl_xor_sync(0xffffffffu, vsum, 4);
                vsq  += __shfl_xor_sync(0xffffffffu, vsq, 4);
                float mean = vsum * (1.0f / 128.0f);
                float var  = vsq * (1.0f / 128.0f) - mean * mean;
                float rstd = rsqrtf(var + 1e-5f);

                long long nd = s_node[nslot * TILE_M + r];
                float* orow = out + nd * NDIM;
#pragma unroll
                for (int j = 0; j < 4; j++) {
                    int cb = (cc + 8 * j) * 4;
                    const float4 g  = *(const float4*)&s_gam[cb];
                    const float4 bt = *(const float4*)&s_bet[cb];
                    float4 o;
                    o.x = (v[j].x - mean) * rstd * g.x + bt.x;
                    o.y = (v[j].y - mean) * rstd * g.y + bt.y;
                    o.z = (v[j].z - mean) * rstd * g.z + bt.z;
                    o.w = (v[j].w - mean) * rstd * g.w + bt.w;
                    *(float4*)&orow[cb] = o;
                }
            }
        }
        // loop-top __syncthreads rejoins kh0/kh1
    }
}

// ============================================================================
// launch
// ============================================================================
extern "C" void kernel_launch(void* const* d_in, const int* in_sizes, int n_in,
                              void* d_out, int out_size) {
    const int*   node_ids = (const int*)  d_in[0];
    const float* messages = (const float*)d_in[1];
    const float* node_mem = (const float*)d_in[2];
    const float* conv_w   = (const float*)d_in[3];
    const float* lin_w    = (const float*)d_in[4];
    const float* lin_b    = (const float*)d_in[5];
    const float* ln_g     = (const float*)d_in[6];
    const float* ln_bt    = (const float*)d_in[7];
    float* out = (float*)d_out;

    int Btot    = in_sizes[1] / NDIM;            // 262144
    int ntiles  = Btot / TILE_M;                 // 4096
    int period  = in_sizes[3] / KDIM;            // 7
    int pad     = period / 2;                    // 3 (L == 1 path)
    int nf4     = out_size / 4;

    // mask of rows updated by the scatter
    k_clear<<<64, 256>>>((1 << 20) / 16);
    k_mark<<<(Btot + 255) / 256, 256>>>(node_ids, Btot);

    // copy non-updated rows at full occupancy
    k_copy_masked<<<2048, 256>>>((const float4*)node_mem, (float4*)out, nf4);

    // persistent GEMM + LN + scatter
    const int dyn_smem = 2 * TILE_M * SX_STRIDE * 4       // x ping-pong
                       + 2048 * 16                        // s_comb
                       + TILE_M * SD_STRIDE * 4           // sD
                       + NSLOTS * TILE_M * 4 + 2 * NDIM * 4;
    static int configured = -1;
    if (configured != dyn_smem) {
        cudaFuncSetAttribute(rhythm_gemm, cudaFuncAttributeMaxDynamicSharedMemorySize,
                             dyn_smem);
        configured = dyn_smem;
    }
    rhythm_gemm<<<NCTAS, NTHREADS, dyn_smem>>>(node_ids, messages, node_mem, conv_w,
                                               lin_w, lin_b, ln_g, ln_bt, out,
                                               ntiles, period, pad);
}